// round 9
// baseline (speedup 1.0000x reference)
#include <cuda_runtime.h>
#include <cuda_bf16.h>
#include <cstdint>

// Problem constants (fixed by dataset)
#define BATCH   131072
#define UNITS   512
#define DIMK    64
#define M_TILE  64
#define N_TILES (BATCH / M_TILE)   // 2048
#define GRID_X  296                // 2 CTAs per SM
#define NTHREADS 256               // 8 warps; each warp owns a 64-col strip

// ---------------- SMEM layout ----------------
static constexpr int ROW_BYTES = 144;                 // bf16 rows padded (ldmatrix)
// steady-state region
static constexpr int SM_WSQ  = 0;                     // 512 f32 -> 2048
static constexpr int SM_STG  = 2048;                  // 8 warps * 2KB -> 18432
static constexpr int SM_XSQ0 = 18432;                 // 64 f32 -> 18688
static constexpr int SM_XSQ1 = 18688;                 // 64 f32 -> 18944
static constexpr int SM_X0   = 19456;                 // 64*144 = 9216 -> 28672
static constexpr int SM_X1   = 28672;                 // 9216 -> 37888
// init-only region (overlays STG/XSQ/X; used before first x tile is staged)
static constexpr int SM_WST  = 2048;                  // 512*144 = 73728 -> 75776
static constexpr int SMEM_TOTAL = 75776;

static __device__ __forceinline__ uint32_t smem_u32(const void* p) {
    uint32_t a;
    asm("{ .reg .u64 t; cvta.to.shared.u64 t, %1; cvt.u32.u64 %0, t; }" : "=r"(a) : "l"(p));
    return a;
}

static __device__ __forceinline__ void ldsm_x4(uint32_t& r0, uint32_t& r1, uint32_t& r2,
                                               uint32_t& r3, uint32_t addr) {
    asm volatile("ldmatrix.sync.aligned.m8n8.x4.shared.b16 {%0,%1,%2,%3}, [%4];"
                 : "=r"(r0), "=r"(r1), "=r"(r2), "=r"(r3) : "r"(addr));
}

static __device__ __forceinline__ void mma_bf16(float c[4], uint32_t a0, uint32_t a1,
                                                uint32_t a2, uint32_t a3,
                                                uint32_t b0, uint32_t b1) {
    asm volatile(
        "mma.sync.aligned.m16n8k16.row.col.f32.bf16.bf16.f32 "
        "{%0,%1,%2,%3}, {%4,%5,%6,%7}, {%8,%9}, {%0,%1,%2,%3};"
        : "+f"(c[0]), "+f"(c[1]), "+f"(c[2]), "+f"(c[3])
        : "r"(a0), "r"(a1), "r"(a2), "r"(a3), "r"(b0), "r"(b1));
}

static __device__ __forceinline__ uint32_t pack_bf16(float a, float b) {
    __nv_bfloat162 t = __floats2bfloat162_rn(a, b);
    return *reinterpret_cast<uint32_t*>(&t);
}

static __device__ __forceinline__ float bf_lo(uint32_t u) {
    return __uint_as_float(u << 16);
}
static __device__ __forceinline__ float bf_hi(uint32_t u) {
    return __uint_as_float(u & 0xffff0000u);
}

__global__ void __launch_bounds__(NTHREADS, 2)
l2dist_kernel(const float* __restrict__ x, const float* __restrict__ w,
              float* __restrict__ out) {
    extern __shared__ char smem[];
    const uint32_t sb = smem_u32(smem);
    const int tid  = threadIdx.x;
    const int wid  = tid >> 5;
    const int lane = tid & 31;

    // ---- Stage W -> bf16 SMEM (init-only region) + exact fp32 ||w||^2 ----
    #pragma unroll
    for (int rr = 0; rr < 2; rr++) {
        const int u = rr * NTHREADS + tid;
        const float* wr = w + (size_t)u * DIMK;
        float sq = 0.f;
        #pragma unroll
        for (int g = 0; g < 8; g++) {
            float4 a = *reinterpret_cast<const float4*>(wr + 8 * g);
            float4 b = *reinterpret_cast<const float4*>(wr + 8 * g + 4);
            sq += a.x * a.x + a.y * a.y + a.z * a.z + a.w * a.w
                + b.x * b.x + b.y * b.y + b.z * b.z + b.w * b.w;
            uint4 pk;
            pk.x = pack_bf16(a.x, a.y); pk.y = pack_bf16(a.z, a.w);
            pk.z = pack_bf16(b.x, b.y); pk.w = pack_bf16(b.z, b.w);
            *reinterpret_cast<uint4*>(smem + SM_WST + u * ROW_BYTES + g * 16) = pk;
        }
        *reinterpret_cast<float*>(smem + SM_WSQ + u * 4) = sq;
    }
    __syncthreads();

    // ---- Load this warp's B fragments ONCE (64 cols x 64 k) : 64 regs ----
    const int n_w = wid * 64;
    uint32_t Bf[4][4][4];   // [n16-group][ks][frag]
    {
        const uint32_t bb = sb + SM_WST + (uint32_t)(lane & 15) * ROW_BYTES
                          + (uint32_t)((lane >> 4) * 16);
        #pragma unroll
        for (int g = 0; g < 4; g++)
            #pragma unroll
            for (int ks = 0; ks < 4; ks++)
                ldsm_x4(Bf[g][ks][0], Bf[g][ks][1], Bf[g][ks][2], Bf[g][ks][3],
                        bb + (uint32_t)(n_w + g * 16) * ROW_BYTES + ks * 32);
    }

    const int gq = lane >> 2;           // 0..7  (C-frag row within 8-group)
    const int qq = lane & 3;            // 0..3  (C-frag col pair)

    // readback/store mapping: lane covers 4 consecutive cols of 2 rows per iter
    const int r16 = lane >> 4;          // 0/1
    const int c16 = lane & 15;          // 0..15 -> cols c16*4..+3
    const float4 ws4 = *reinterpret_cast<const float4*>(
        smem + SM_WSQ + (n_w + c16 * 4) * 4);

    // W staging no longer needed; steady-state buffers may overwrite it.
    __syncthreads();

    const uint32_t a_lane_off = (uint32_t)(lane & 15) * ROW_BYTES
                              + (uint32_t)((lane >> 4) * 16);
    char* const stg = smem + SM_STG + wid * 2048;
    const int rd_g  = c16 >> 1;         // 16B granule 0..7
    const int rd_h8 = c16 & 1;          // 8B half within granule

    const int ld_r0 = tid >> 4;         // 0..15
    const int ld_k  = (tid & 15) * 4;

    int t = blockIdx.x;

    // ---- Preload first tile into buffer 0 ----
    if (t < N_TILES) {
        #pragma unroll
        for (int it = 0; it < 4; it++) {
            const int r = it * 16 + ld_r0;
            float4 v = __ldcs(reinterpret_cast<const float4*>(
                x + (size_t)(t * M_TILE + r) * DIMK + ld_k));
            float sq = v.x * v.x + v.y * v.y + v.z * v.z + v.w * v.w;
            sq += __shfl_xor_sync(0xffffffffu, sq, 1);
            sq += __shfl_xor_sync(0xffffffffu, sq, 2);
            sq += __shfl_xor_sync(0xffffffffu, sq, 4);
            sq += __shfl_xor_sync(0xffffffffu, sq, 8);
            uint2 pk; pk.x = pack_bf16(v.x, v.y); pk.y = pack_bf16(v.z, v.w);
            *reinterpret_cast<uint2*>(smem + SM_X0 + r * ROW_BYTES + ld_k * 2) = pk;
            if ((tid & 15) == 0)
                *reinterpret_cast<float*>(smem + SM_XSQ0 + r * 4) = sq;
        }
    }
    __syncthreads();

    int cur = 0;
    for (; t < N_TILES; t += GRID_X, cur ^= 1) {
        const int tn = t + GRID_X;
        const bool more = (tn < N_TILES);
        const uint32_t xb = cur ? SM_X1 : SM_X0;
        const uint32_t xq = cur ? SM_XSQ1 : SM_XSQ0;
        const int row0 = t * M_TILE;

        // ---- Prefetch next tile's x into registers ----
        float4 pvA[2], pvB[2];
        if (more) {
            #pragma unroll
            for (int it = 0; it < 2; it++)
                pvA[it] = __ldcs(reinterpret_cast<const float4*>(
                    x + (size_t)(tn * M_TILE + it * 16 + ld_r0) * DIMK + ld_k));
        }

        #pragma unroll
        for (int rb = 0; rb < 4; rb++) {
            if (rb == 2 && more) {
                #pragma unroll
                for (int it = 0; it < 2; it++)
                    pvB[it] = __ldcs(reinterpret_cast<const float4*>(
                        x + (size_t)(tn * M_TILE + (it + 2) * 16 + ld_r0) * DIMK + ld_k));
            }

            const uint32_t abase = sb + xb + (uint32_t)(rb * 16) * ROW_BYTES + a_lane_off;
            float acc[8][4];
            #pragma unroll
            for (int i = 0; i < 8; i++)
                #pragma unroll
                for (int j = 0; j < 4; j++) acc[i][j] = 0.f;

            #pragma unroll
            for (int ks = 0; ks < 4; ks++) {
                uint32_t a0, a1, a2, a3;
                ldsm_x4(a0, a1, a2, a3, abase + ks * 32);
                #pragma unroll
                for (int g = 0; g < 4; g++) {
                    mma_bf16(acc[2 * g + 0], a0, a1, a2, a3, Bf[g][ks][0], Bf[g][ks][2]);
                    mma_bf16(acc[2 * g + 1], a0, a1, a2, a3, Bf[g][ks][1], Bf[g][ks][3]);
                }
            }

            // ---- Stage acc as bf16x2: row stride 128B, granule p = nb ^ gq ----
            #pragma unroll
            for (int nb = 0; nb < 8; nb++) {
                const uint32_t goff = (uint32_t)((nb ^ gq) * 16 + qq * 4);
                *reinterpret_cast<uint32_t*>(stg + gq * 128 + goff)
                    = pack_bf16(acc[nb][0], acc[nb][1]);
                *reinterpret_cast<uint32_t*>(stg + (gq + 8) * 128 + goff)
                    = pack_bf16(acc[nb][2], acc[nb][3]);
            }
            __syncwarp();

            // ---- Read back (LDS.64), unpack, epilogue, full-line STG.128 ----
            #pragma unroll
            for (int i = 0; i < 8; i++) {
                const int row = i * 2 + r16;
                const uint32_t p = (uint32_t)(rd_g ^ (row & 7));
                const uint2 u = *reinterpret_cast<const uint2*>(
                    stg + row * 128 + p * 16 + rd_h8 * 8);
                const float xsv = *reinterpret_cast<const float*>(
                    smem + xq + (rb * 16 + row) * 4);
                float4 o;
                o.x = fmaf(-2.f, bf_lo(u.x), xsv + ws4.x);
                o.y = fmaf(-2.f, bf_hi(u.x), xsv + ws4.y);
                o.z = fmaf(-2.f, bf_lo(u.y), xsv + ws4.z);
                o.w = fmaf(-2.f, bf_hi(u.y), xsv + ws4.w);
                __stcs(reinterpret_cast<float4*>(
                    out + (size_t)(row0 + rb * 16 + row) * UNITS + n_w + c16 * 4), o);
            }
            __syncwarp();
        }

        // ---- Commit prefetched tile to the other buffer ----
        if (more) {
            const uint32_t xbn = cur ? SM_X0 : SM_X1;
            const uint32_t xqn = cur ? SM_XSQ0 : SM_XSQ1;
            #pragma unroll
            for (int it = 0; it < 4; it++) {
                const int r = it * 16 + ld_r0;
                float4 v = (it < 2) ? pvA[it] : pvB[it - 2];
                float sq = v.x * v.x + v.y * v.y + v.z * v.z + v.w * v.w;
                sq += __shfl_xor_sync(0xffffffffu, sq, 1);
                sq += __shfl_xor_sync(0xffffffffu, sq, 2);
                sq += __shfl_xor_sync(0xffffffffu, sq, 4);
                sq += __shfl_xor_sync(0xffffffffu, sq, 8);
                uint2 pk; pk.x = pack_bf16(v.x, v.y); pk.y = pack_bf16(v.z, v.w);
                *reinterpret_cast<uint2*>(smem + xbn + r * ROW_BYTES + ld_k * 2) = pk;
                if ((tid & 15) == 0)
                    *reinterpret_cast<float*>(smem + xqn + r * 4) = sq;
            }
        }
        __syncthreads();
    }
}

extern "C" void kernel_launch(void* const* d_in, const int* in_sizes, int n_in,
                              void* d_out, int out_size) {
    const float* x = (const float*)d_in[0];
    const float* w = (const float*)d_in[1];
    float* out = (float*)d_out;
    cudaFuncSetAttribute(l2dist_kernel, cudaFuncAttributeMaxDynamicSharedMemorySize, SMEM_TOTAL);
    l2dist_kernel<<<GRID_X, NTHREADS, SMEM_TOTAL>>>(x, w, out);
}

// round 10
// speedup vs baseline: 1.0303x; 1.0303x over previous
#include <cuda_runtime.h>
#include <cuda_bf16.h>
#include <cstdint>

// Problem constants (fixed by dataset)
#define BATCH   131072
#define UNITS   512
#define DIMK    64
#define M_TILE  128
#define N_TILES (BATCH / M_TILE)   // 1024
#define GRID_X  148
#define NTHREADS 256               // 8 warps; each warp owns a 64-col strip

// ---------------- SMEM layout ----------------
static constexpr int ROW_BYTES = 144;                     // bf16 rows padded (ldmatrix)
static constexpr int SM_WSQ  = 0;                         // 512 f32 -> 2048
static constexpr int SM_XSQ0 = 2048;                      // 128 f32 -> 2560
static constexpr int SM_XSQ1 = 2560;                      // 128 f32 -> 3072
static constexpr int SM_X0   = 3072;                      // 128*144 -> 21504
static constexpr int SM_X1   = 21504;                     // -> 39936
static constexpr int SM_WST  = 39936;                     // 512*144 -> 113664
static constexpr int SM_STG  = 113664;                    // 8 warps * 2 * 2KB -> 146432
static constexpr int SMEM_TOTAL = SM_STG + 8 * 4096;

static __device__ __forceinline__ uint32_t smem_u32(const void* p) {
    uint32_t a;
    asm("{ .reg .u64 t; cvta.to.shared.u64 t, %1; cvt.u32.u64 %0, t; }" : "=r"(a) : "l"(p));
    return a;
}

static __device__ __forceinline__ void ldsm_x4(uint32_t& r0, uint32_t& r1, uint32_t& r2,
                                               uint32_t& r3, uint32_t addr) {
    asm volatile("ldmatrix.sync.aligned.m8n8.x4.shared.b16 {%0,%1,%2,%3}, [%4];"
                 : "=r"(r0), "=r"(r1), "=r"(r2), "=r"(r3) : "r"(addr));
}

static __device__ __forceinline__ void mma_bf16(float c[4], uint32_t a0, uint32_t a1,
                                                uint32_t a2, uint32_t a3,
                                                uint32_t b0, uint32_t b1) {
    asm volatile(
        "mma.sync.aligned.m16n8k16.row.col.f32.bf16.bf16.f32 "
        "{%0,%1,%2,%3}, {%4,%5,%6,%7}, {%8,%9}, {%0,%1,%2,%3};"
        : "+f"(c[0]), "+f"(c[1]), "+f"(c[2]), "+f"(c[3])
        : "r"(a0), "r"(a1), "r"(a2), "r"(a3), "r"(b0), "r"(b1));
}

static __device__ __forceinline__ uint32_t pack_bf16(float a, float b) {
    __nv_bfloat162 t = __floats2bfloat162_rn(a, b);
    return *reinterpret_cast<uint32_t*>(&t);
}

static __device__ __forceinline__ float bf_lo(uint32_t u) {
    return __uint_as_float(u << 16);
}
static __device__ __forceinline__ float bf_hi(uint32_t u) {
    return __uint_as_float(u & 0xffff0000u);
}

__global__ void __launch_bounds__(NTHREADS, 1)
l2dist_kernel(const float* __restrict__ x, const float* __restrict__ w,
              float* __restrict__ out) {
    extern __shared__ char smem[];
    const uint32_t sb = smem_u32(smem);
    const int tid  = threadIdx.x;
    const int wid  = tid >> 5;
    const int lane = tid & 31;

    // ---- Stage W -> bf16 SMEM (padded rows) + exact fp32 ||w||^2 ----
    #pragma unroll
    for (int rr = 0; rr < 2; rr++) {
        const int u = rr * NTHREADS + tid;
        const float* wr = w + (size_t)u * DIMK;
        float sq = 0.f;
        #pragma unroll
        for (int g = 0; g < 8; g++) {
            float4 a = *reinterpret_cast<const float4*>(wr + 8 * g);
            float4 b = *reinterpret_cast<const float4*>(wr + 8 * g + 4);
            sq += a.x * a.x + a.y * a.y + a.z * a.z + a.w * a.w
                + b.x * b.x + b.y * b.y + b.z * b.z + b.w * b.w;
            uint4 pk;
            pk.x = pack_bf16(a.x, a.y); pk.y = pack_bf16(a.z, a.w);
            pk.z = pack_bf16(b.x, b.y); pk.w = pack_bf16(b.z, b.w);
            *reinterpret_cast<uint4*>(smem + SM_WST + u * ROW_BYTES + g * 16) = pk;
        }
        *reinterpret_cast<float*>(smem + SM_WSQ + u * 4) = sq;
    }
    __syncthreads();

    // ---- Load this warp's B fragments ONCE (64 cols x 64 k) : 64 regs ----
    const int n_w = wid * 64;
    uint32_t Bf[4][4][4];   // [n16-group][ks][frag]
    {
        const uint32_t bb = sb + SM_WST + (uint32_t)(lane & 15) * ROW_BYTES
                          + (uint32_t)((lane >> 4) * 16);
        #pragma unroll
        for (int g = 0; g < 4; g++)
            #pragma unroll
            for (int ks = 0; ks < 4; ks++)
                ldsm_x4(Bf[g][ks][0], Bf[g][ks][1], Bf[g][ks][2], Bf[g][ks][3],
                        bb + (uint32_t)(n_w + g * 16) * ROW_BYTES + ks * 32);
    }

    const int gq = lane >> 2;           // 0..7  (C-frag row within 8-group)
    const int qq = lane & 3;            // 0..3  (C-frag col pair)

    // readback/store mapping: lane covers 4 consecutive cols of 2 rows per iter
    const int r16 = lane >> 4;          // 0/1
    const int c16 = lane & 15;          // 0..15 -> cols c16*4..+3
    const float4 ws4 = *reinterpret_cast<const float4*>(
        smem + SM_WSQ + (n_w + c16 * 4) * 4);

    const uint32_t a_lane_off = (uint32_t)(lane & 15) * ROW_BYTES
                              + (uint32_t)((lane >> 4) * 16);
    char* const stg0 = smem + SM_STG + wid * 4096;      // two 2KB buffers
    const int rd_g  = c16 >> 1;         // 16B granule 0..7
    const int rd_h8 = c16 & 1;          // 8B half within granule

    const int ld_r0 = tid >> 4;
    const int ld_k  = (tid & 15) * 4;

    int t = blockIdx.x;

    // ---- Preload first tile into buffer 0 ----
    if (t < N_TILES) {
        #pragma unroll
        for (int it = 0; it < 8; it++) {
            const int r = it * 16 + ld_r0;
            float4 v = __ldcs(reinterpret_cast<const float4*>(
                x + (size_t)(t * M_TILE + r) * DIMK + ld_k));
            float sq = v.x * v.x + v.y * v.y + v.z * v.z + v.w * v.w;
            sq += __shfl_xor_sync(0xffffffffu, sq, 1);
            sq += __shfl_xor_sync(0xffffffffu, sq, 2);
            sq += __shfl_xor_sync(0xffffffffu, sq, 4);
            sq += __shfl_xor_sync(0xffffffffu, sq, 8);
            uint2 pk; pk.x = pack_bf16(v.x, v.y); pk.y = pack_bf16(v.z, v.w);
            *reinterpret_cast<uint2*>(smem + SM_X0 + r * ROW_BYTES + ld_k * 2) = pk;
            if ((tid & 15) == 0)
                *reinterpret_cast<float*>(smem + SM_XSQ0 + r * 4) = sq;
        }
    }
    __syncthreads();

    int cur = 0;
    for (; t < N_TILES; t += GRID_X, cur ^= 1) {
        const int tn = t + GRID_X;
        const bool more = (tn < N_TILES);
        const uint32_t xb = cur ? SM_X1 : SM_X0;
        const uint32_t xq = cur ? SM_XSQ1 : SM_XSQ0;
        const int row0 = t * M_TILE;

        float4 pvA[4], pvB[4];
        if (more) {
            #pragma unroll
            for (int it = 0; it < 4; it++)
                pvA[it] = __ldcs(reinterpret_cast<const float4*>(
                    x + (size_t)(tn * M_TILE + it * 16 + ld_r0) * DIMK + ld_k));
        }

        #pragma unroll
        for (int rb = 0; rb < 8; rb++) {
            if (rb == 4 && more) {
                #pragma unroll
                for (int it = 0; it < 4; it++)
                    pvB[it] = __ldcs(reinterpret_cast<const float4*>(
                        x + (size_t)(tn * M_TILE + (it + 4) * 16 + ld_r0) * DIMK + ld_k));
            }

            char* const stg = stg0 + (rb & 1) * 2048;    // double-buffered staging
            const uint32_t abase = sb + xb + (uint32_t)(rb * 16) * ROW_BYTES + a_lane_off;
            float acc[8][4];
            #pragma unroll
            for (int i = 0; i < 8; i++)
                #pragma unroll
                for (int j = 0; j < 4; j++) acc[i][j] = 0.f;

            #pragma unroll
            for (int ks = 0; ks < 4; ks++) {
                uint32_t a0, a1, a2, a3;
                ldsm_x4(a0, a1, a2, a3, abase + ks * 32);
                #pragma unroll
                for (int g = 0; g < 4; g++) {
                    mma_bf16(acc[2 * g + 0], a0, a1, a2, a3, Bf[g][ks][0], Bf[g][ks][2]);
                    mma_bf16(acc[2 * g + 1], a0, a1, a2, a3, Bf[g][ks][1], Bf[g][ks][3]);
                }
            }

            // ---- Stage acc as bf16x2: row stride 128B, granule p = nb ^ gq ----
            #pragma unroll
            for (int nb = 0; nb < 8; nb++) {
                const uint32_t goff = (uint32_t)((nb ^ gq) * 16 + qq * 4);
                *reinterpret_cast<uint32_t*>(stg + gq * 128 + goff)
                    = pack_bf16(acc[nb][0], acc[nb][1]);
                *reinterpret_cast<uint32_t*>(stg + (gq + 8) * 128 + goff)
                    = pack_bf16(acc[nb][2], acc[nb][3]);
            }
            __syncwarp();
            // NOTE: no trailing syncwarp — next rb writes the other buffer, so
            // its ldsm/MMA/STS overlap this rb's readback + global stores.

            // ---- Read back (LDS.64), unpack, epilogue, full-line STG.128 ----
            #pragma unroll
            for (int i = 0; i < 8; i++) {
                const int row = i * 2 + r16;
                const uint32_t p = (uint32_t)(rd_g ^ (row & 7));
                const uint2 u = *reinterpret_cast<const uint2*>(
                    stg + row * 128 + p * 16 + rd_h8 * 8);
                const float xsv = *reinterpret_cast<const float*>(
                    smem + xq + (rb * 16 + row) * 4);
                float4 o;
                o.x = fmaf(-2.f, bf_lo(u.x), xsv + ws4.x);
                o.y = fmaf(-2.f, bf_hi(u.x), xsv + ws4.y);
                o.z = fmaf(-2.f, bf_lo(u.y), xsv + ws4.z);
                o.w = fmaf(-2.f, bf_hi(u.y), xsv + ws4.w);
                __stcs(reinterpret_cast<float4*>(
                    out + (size_t)(row0 + rb * 16 + row) * UNITS + n_w + c16 * 4), o);
            }
        }

        // ---- Commit prefetched tile to the other buffer ----
        if (more) {
            const uint32_t xbn = cur ? SM_X0 : SM_X1;
            const uint32_t xqn = cur ? SM_XSQ0 : SM_XSQ1;
            #pragma unroll
            for (int it = 0; it < 8; it++) {
                const int r = it * 16 + ld_r0;
                float4 v = (it < 4) ? pvA[it] : pvB[it - 4];
                float sq = v.x * v.x + v.y * v.y + v.z * v.z + v.w * v.w;
                sq += __shfl_xor_sync(0xffffffffu, sq, 1);
                sq += __shfl_xor_sync(0xffffffffu, sq, 2);
                sq += __shfl_xor_sync(0xffffffffu, sq, 4);
                sq += __shfl_xor_sync(0xffffffffu, sq, 8);
                uint2 pk; pk.x = pack_bf16(v.x, v.y); pk.y = pack_bf16(v.z, v.w);
                *reinterpret_cast<uint2*>(smem + xbn + r * ROW_BYTES + ld_k * 2) = pk;
                if ((tid & 15) == 0)
                    *reinterpret_cast<float*>(smem + xqn + r * 4) = sq;
            }
        }
        __syncthreads();
    }
}

extern "C" void kernel_launch(void* const* d_in, const int* in_sizes, int n_in,
                              void* d_out, int out_size) {
    const float* x = (const float*)d_in[0];
    const float* w = (const float*)d_in[1];
    float* out = (float*)d_out;
    cudaFuncSetAttribute(l2dist_kernel, cudaFuncAttributeMaxDynamicSharedMemorySize, SMEM_TOTAL);
    l2dist_kernel<<<GRID_X, NTHREADS, SMEM_TOTAL>>>(x, w, out);
}

// round 11
// speedup vs baseline: 1.0792x; 1.0474x over previous
#include <cuda_runtime.h>
#include <cuda_bf16.h>
#include <cstdint>

// Problem constants (fixed by dataset)
#define BATCH   131072
#define UNITS   512
#define DIMK    64
#define M_TILE  128
#define N_TILES (BATCH / M_TILE)   // 1024
#define GRID_X  148
#define NTHREADS 256               // 8 warps; each warp owns a 64-col strip

// ---------------- SMEM layout ----------------
static constexpr int ROW_BYTES = 144;                     // bf16 rows padded (ldmatrix)
static constexpr int SM_WSQ  = 0;                         // 512 f32 -> 2048
static constexpr int SM_XSQ0 = 2048;                      // 128 f32 -> 2560
static constexpr int SM_XSQ1 = 2560;                      // 128 f32 -> 3072
static constexpr int SM_X0   = 3072;                      // 128*144 -> 21504
static constexpr int SM_X1   = 21504;                     // -> 39936
static constexpr int SM_WST  = 39936;                     // 512*144 -> 113664
static constexpr int SM_STG  = 113664;                    // 8 warps * 2 * 4KB -> 179200
static constexpr int SMEM_TOTAL = SM_STG + 8 * 8192;

static __device__ __forceinline__ uint32_t smem_u32(const void* p) {
    uint32_t a;
    asm("{ .reg .u64 t; cvta.to.shared.u64 t, %1; cvt.u32.u64 %0, t; }" : "=r"(a) : "l"(p));
    return a;
}

static __device__ __forceinline__ void ldsm_x4(uint32_t& r0, uint32_t& r1, uint32_t& r2,
                                               uint32_t& r3, uint32_t addr) {
    asm volatile("ldmatrix.sync.aligned.m8n8.x4.shared.b16 {%0,%1,%2,%3}, [%4];"
                 : "=r"(r0), "=r"(r1), "=r"(r2), "=r"(r3) : "r"(addr));
}

static __device__ __forceinline__ void mma_bf16(float c[4], uint32_t a0, uint32_t a1,
                                                uint32_t a2, uint32_t a3,
                                                uint32_t b0, uint32_t b1) {
    asm volatile(
        "mma.sync.aligned.m16n8k16.row.col.f32.bf16.bf16.f32 "
        "{%0,%1,%2,%3}, {%4,%5,%6,%7}, {%8,%9}, {%0,%1,%2,%3};"
        : "+f"(c[0]), "+f"(c[1]), "+f"(c[2]), "+f"(c[3])
        : "r"(a0), "r"(a1), "r"(a2), "r"(a3), "r"(b0), "r"(b1));
}

static __device__ __forceinline__ uint32_t pack_bf16(float a, float b) {
    __nv_bfloat162 t = __floats2bfloat162_rn(a, b);
    return *reinterpret_cast<uint32_t*>(&t);
}

__global__ void __launch_bounds__(NTHREADS, 1)
l2dist_kernel(const float* __restrict__ x, const float* __restrict__ w,
              float* __restrict__ out) {
    extern __shared__ char smem[];
    const uint32_t sb = smem_u32(smem);
    const int tid  = threadIdx.x;
    const int wid  = tid >> 5;
    const int lane = tid & 31;

    // ---- Stage W -> bf16 SMEM (padded rows) + exact fp32 ||w||^2 ----
    #pragma unroll
    for (int rr = 0; rr < 2; rr++) {
        const int u = rr * NTHREADS + tid;
        const float* wr = w + (size_t)u * DIMK;
        float sq = 0.f;
        #pragma unroll
        for (int g = 0; g < 8; g++) {
            float4 a = *reinterpret_cast<const float4*>(wr + 8 * g);
            float4 b = *reinterpret_cast<const float4*>(wr + 8 * g + 4);
            sq += a.x * a.x + a.y * a.y + a.z * a.z + a.w * a.w
                + b.x * b.x + b.y * b.y + b.z * b.z + b.w * b.w;
            uint4 pk;
            pk.x = pack_bf16(a.x, a.y); pk.y = pack_bf16(a.z, a.w);
            pk.z = pack_bf16(b.x, b.y); pk.w = pack_bf16(b.z, b.w);
            *reinterpret_cast<uint4*>(smem + SM_WST + u * ROW_BYTES + g * 16) = pk;
        }
        *reinterpret_cast<float*>(smem + SM_WSQ + u * 4) = sq;
    }
    __syncthreads();

    // ---- Load this warp's B fragments ONCE (64 cols x 64 k) : 64 regs ----
    const int n_w = wid * 64;
    uint32_t Bf[4][4][4];   // [n16-group][ks][frag]
    {
        const uint32_t bb = sb + SM_WST + (uint32_t)(lane & 15) * ROW_BYTES
                          + (uint32_t)((lane >> 4) * 16);
        #pragma unroll
        for (int g = 0; g < 4; g++)
            #pragma unroll
            for (int ks = 0; ks < 4; ks++)
                ldsm_x4(Bf[g][ks][0], Bf[g][ks][1], Bf[g][ks][2], Bf[g][ks][3],
                        bb + (uint32_t)(n_w + g * 16) * ROW_BYTES + ks * 32);
    }

    const int gq = lane >> 2;           // 0..7  (C-frag row within 8-group)
    const int qq = lane & 3;            // 0..3  (C-frag col pair)

    // readback/store mapping: lane covers 4 consecutive cols of 2 rows per iter
    const int rd_row  = lane >> 4;      // 0/1
    const int rd_colg = lane & 15;      // 0..15 -> cols rd_colg*4..+3
    const float4 ws4 = *reinterpret_cast<const float4*>(
        smem + SM_WSQ + (n_w + rd_colg * 4) * 4);

    const uint32_t a_lane_off = (uint32_t)(lane & 15) * ROW_BYTES
                              + (uint32_t)((lane >> 4) * 16);
    char* const stg0 = smem + SM_STG + wid * 8192;   // two 4KB fp32 buffers

    const int ld_r0 = tid >> 4;
    const int ld_k  = (tid & 15) * 4;

    int t = blockIdx.x;

    // ---- Preload first tile into buffer 0 ----
    if (t < N_TILES) {
        #pragma unroll
        for (int it = 0; it < 8; it++) {
            const int r = it * 16 + ld_r0;
            float4 v = __ldcs(reinterpret_cast<const float4*>(
                x + (size_t)(t * M_TILE + r) * DIMK + ld_k));
            float sq = v.x * v.x + v.y * v.y + v.z * v.z + v.w * v.w;
            sq += __shfl_xor_sync(0xffffffffu, sq, 1);
            sq += __shfl_xor_sync(0xffffffffu, sq, 2);
            sq += __shfl_xor_sync(0xffffffffu, sq, 4);
            sq += __shfl_xor_sync(0xffffffffu, sq, 8);
            uint2 pk; pk.x = pack_bf16(v.x, v.y); pk.y = pack_bf16(v.z, v.w);
            *reinterpret_cast<uint2*>(smem + SM_X0 + r * ROW_BYTES + ld_k * 2) = pk;
            if ((tid & 15) == 0)
                *reinterpret_cast<float*>(smem + SM_XSQ0 + r * 4) = sq;
        }
    }
    __syncthreads();

    int cur = 0;
    for (; t < N_TILES; t += GRID_X, cur ^= 1) {
        const int tn = t + GRID_X;
        const bool more = (tn < N_TILES);
        const uint32_t xb = cur ? SM_X1 : SM_X0;
        const uint32_t xq = cur ? SM_XSQ1 : SM_XSQ0;
        const uint32_t xbn = cur ? SM_X0 : SM_X1;
        const uint32_t xqn = cur ? SM_XSQ0 : SM_XSQ1;
        const int row0 = t * M_TILE;

        float4 pvA[4], pvB[4];
        if (more) {
            #pragma unroll
            for (int it = 0; it < 4; it++)
                pvA[it] = __ldcs(reinterpret_cast<const float4*>(
                    x + (size_t)(tn * M_TILE + it * 16 + ld_r0) * DIMK + ld_k));
        }

        #pragma unroll
        for (int rb = 0; rb < 8; rb++) {
            if (rb == 4 && more) {
                #pragma unroll
                for (int it = 0; it < 4; it++)
                    pvB[it] = __ldcs(reinterpret_cast<const float4*>(
                        x + (size_t)(tn * M_TILE + (it + 4) * 16 + ld_r0) * DIMK + ld_k));
            }
            // spread the next-tile commit: first half at rb==6 (regs pvA freed)
            if (rb == 6 && more) {
                #pragma unroll
                for (int it = 0; it < 4; it++) {
                    const int r = it * 16 + ld_r0;
                    float4 v = pvA[it];
                    float sq = v.x * v.x + v.y * v.y + v.z * v.z + v.w * v.w;
                    sq += __shfl_xor_sync(0xffffffffu, sq, 1);
                    sq += __shfl_xor_sync(0xffffffffu, sq, 2);
                    sq += __shfl_xor_sync(0xffffffffu, sq, 4);
                    sq += __shfl_xor_sync(0xffffffffu, sq, 8);
                    uint2 pk; pk.x = pack_bf16(v.x, v.y); pk.y = pack_bf16(v.z, v.w);
                    *reinterpret_cast<uint2*>(smem + xbn + r * ROW_BYTES + ld_k * 2) = pk;
                    if ((tid & 15) == 0)
                        *reinterpret_cast<float*>(smem + xqn + r * 4) = sq;
                }
            }

            char* const stg = stg0 + (rb & 1) * 4096;   // double-buffered staging
            const uint32_t abase = sb + xb + (uint32_t)(rb * 16) * ROW_BYTES + a_lane_off;
            float acc[8][4];
            #pragma unroll
            for (int i = 0; i < 8; i++)
                #pragma unroll
                for (int j = 0; j < 4; j++) acc[i][j] = 0.f;

            #pragma unroll
            for (int ks = 0; ks < 4; ks++) {
                uint32_t a0, a1, a2, a3;
                ldsm_x4(a0, a1, a2, a3, abase + ks * 32);
                #pragma unroll
                for (int g = 0; g < 4; g++) {
                    mma_bf16(acc[2 * g + 0], a0, a1, a2, a3, Bf[g][ks][0], Bf[g][ks][2]);
                    mma_bf16(acc[2 * g + 1], a0, a1, a2, a3, Bf[g][ks][1], Bf[g][ks][3]);
                }
            }

            // ---- Stage raw fp32 acc (STS.64), 8B granules h ^= (gq<<2) ----
            #pragma unroll
            for (int nb = 0; nb < 8; nb++) {
                const uint32_t h  = (uint32_t)(gq * 32 + nb * 4 + qq) ^ ((uint32_t)gq << 2);
                const uint32_t hh = h + 8 * 32;   // row gq+8: same swizzle
                *reinterpret_cast<float2*>(stg + h * 8)
                    = make_float2(acc[nb][0], acc[nb][1]);
                *reinterpret_cast<float2*>(stg + hh * 8)
                    = make_float2(acc[nb][2], acc[nb][3]);
            }
            __syncwarp();
            // no trailing syncwarp: next rb uses the other staging buffer

            // ---- Read back row-major (LDS.128), epilogue, full-line STG.128 ----
            #pragma unroll
            for (int i = 0; i < 8; i++) {
                const int row = i * 2 + rd_row;
                const uint32_t g16 = (uint32_t)(row * 16 + rd_colg)
                                   ^ (((uint32_t)(row & 7)) << 1);
                const float4 v = *reinterpret_cast<const float4*>(stg + g16 * 16);
                const float xsv = *reinterpret_cast<const float*>(
                    smem + xq + (rb * 16 + row) * 4);
                float4 o;
                o.x = fmaf(-2.f, v.x, xsv + ws4.x);
                o.y = fmaf(-2.f, v.y, xsv + ws4.y);
                o.z = fmaf(-2.f, v.z, xsv + ws4.z);
                o.w = fmaf(-2.f, v.w, xsv + ws4.w);
                // default write-back policy (untested lever; was __stcs)
                *reinterpret_cast<float4*>(
                    out + (size_t)(row0 + rb * 16 + row) * UNITS + n_w + rd_colg * 4) = o;
            }
        }

        // ---- Commit second half of prefetched tile ----
        if (more) {
            #pragma unroll
            for (int it = 4; it < 8; it++) {
                const int r = it * 16 + ld_r0;
                float4 v = pvB[it - 4];
                float sq = v.x * v.x + v.y * v.y + v.z * v.z + v.w * v.w;
                sq += __shfl_xor_sync(0xffffffffu, sq, 1);
                sq += __shfl_xor_sync(0xffffffffu, sq, 2);
                sq += __shfl_xor_sync(0xffffffffu, sq, 4);
                sq += __shfl_xor_sync(0xffffffffu, sq, 8);
                uint2 pk; pk.x = pack_bf16(v.x, v.y); pk.y = pack_bf16(v.z, v.w);
                *reinterpret_cast<uint2*>(smem + xbn + r * ROW_BYTES + ld_k * 2) = pk;
                if ((tid & 15) == 0)
                    *reinterpret_cast<float*>(smem + xqn + r * 4) = sq;
            }
        }
        __syncthreads();
    }
}

extern "C" void kernel_launch(void* const* d_in, const int* in_sizes, int n_in,
                              void* d_out, int out_size) {
    const float* x = (const float*)d_in[0];
    const float* w = (const float*)d_in[1];
    float* out = (float*)d_out;
    cudaFuncSetAttribute(l2dist_kernel, cudaFuncAttributeMaxDynamicSharedMemorySize, SMEM_TOTAL);
    l2dist_kernel<<<GRID_X, NTHREADS, SMEM_TOTAL>>>(x, w, out);
}

// round 12
// speedup vs baseline: 1.0798x; 1.0006x over previous
#include <cuda_runtime.h>
#include <cuda_bf16.h>
#include <cstdint>

// Problem constants (fixed by dataset)
#define BATCH   131072
#define UNITS   512
#define DIMK    64
#define M_TILE  128
#define N_TILES (BATCH / M_TILE)   // 1024
#define GRID_X  148
#define NTHREADS 256               // 8 warps; each warp owns a 64-col strip

// ---------------- SMEM layout ----------------
static constexpr int ROW_BYTES = 144;                     // bf16 rows padded (ldmatrix)
static constexpr int SM_WSQ  = 0;                         // 512 f32 -> 2048
static constexpr int SM_XSQ0 = 2048;                      // 128 f32 -> 2560
static constexpr int SM_XSQ1 = 2560;                      // 128 f32 -> 3072
static constexpr int SM_X0   = 3072;                      // 128*144 -> 21504
static constexpr int SM_X1   = 21504;                     // -> 39936
static constexpr int SM_WST  = 39936;                     // 512*144 -> 113664
static constexpr int SM_STG  = 113664;                    // 8 warps * 2 * 4KB -> 179200
static constexpr int SMEM_TOTAL = SM_STG + 8 * 8192;

static __device__ __forceinline__ uint32_t smem_u32(const void* p) {
    uint32_t a;
    asm("{ .reg .u64 t; cvta.to.shared.u64 t, %1; cvt.u32.u64 %0, t; }" : "=r"(a) : "l"(p));
    return a;
}

static __device__ __forceinline__ void ldsm_x4(uint32_t& r0, uint32_t& r1, uint32_t& r2,
                                               uint32_t& r3, uint32_t addr) {
    asm volatile("ldmatrix.sync.aligned.m8n8.x4.shared.b16 {%0,%1,%2,%3}, [%4];"
                 : "=r"(r0), "=r"(r1), "=r"(r2), "=r"(r3) : "r"(addr));
}

static __device__ __forceinline__ void mma_bf16(float c[4], uint32_t a0, uint32_t a1,
                                                uint32_t a2, uint32_t a3,
                                                uint32_t b0, uint32_t b1) {
    asm volatile(
        "mma.sync.aligned.m16n8k16.row.col.f32.bf16.bf16.f32 "
        "{%0,%1,%2,%3}, {%4,%5,%6,%7}, {%8,%9}, {%0,%1,%2,%3};"
        : "+f"(c[0]), "+f"(c[1]), "+f"(c[2]), "+f"(c[3])
        : "r"(a0), "r"(a1), "r"(a2), "r"(a3), "r"(b0), "r"(b1));
}

static __device__ __forceinline__ uint32_t pack_bf16(float a, float b) {
    __nv_bfloat162 t = __floats2bfloat162_rn(a, b);
    return *reinterpret_cast<uint32_t*>(&t);
}

__global__ void __launch_bounds__(NTHREADS, 1)
l2dist_kernel(const float* __restrict__ x, const float* __restrict__ w,
              float* __restrict__ out) {
    extern __shared__ char smem[];
    const uint32_t sb = smem_u32(smem);
    const int tid  = threadIdx.x;
    const int wid  = tid >> 5;
    const int lane = tid & 31;

    const int ld_r0 = tid >> 4;
    const int ld_k  = (tid & 15) * 4;

    int t = blockIdx.x;

    // ---- Issue first tile's x LDG EARLY: latency hides under W staging ----
    float4 fv[8];
    if (t < N_TILES) {
        #pragma unroll
        for (int it = 0; it < 8; it++)
            fv[it] = __ldcs(reinterpret_cast<const float4*>(
                x + (size_t)(t * M_TILE + it * 16 + ld_r0) * DIMK + ld_k));
    }

    // ---- Stage W -> bf16 SMEM (padded rows) + exact fp32 ||w||^2 ----
    #pragma unroll
    for (int rr = 0; rr < 2; rr++) {
        const int u = rr * NTHREADS + tid;
        const float* wr = w + (size_t)u * DIMK;
        float sq = 0.f;
        #pragma unroll
        for (int g = 0; g < 8; g++) {
            float4 a = *reinterpret_cast<const float4*>(wr + 8 * g);
            float4 b = *reinterpret_cast<const float4*>(wr + 8 * g + 4);
            sq += a.x * a.x + a.y * a.y + a.z * a.z + a.w * a.w
                + b.x * b.x + b.y * b.y + b.z * b.z + b.w * b.w;
            uint4 pk;
            pk.x = pack_bf16(a.x, a.y); pk.y = pack_bf16(a.z, a.w);
            pk.z = pack_bf16(b.x, b.y); pk.w = pack_bf16(b.z, b.w);
            *reinterpret_cast<uint4*>(smem + SM_WST + u * ROW_BYTES + g * 16) = pk;
        }
        *reinterpret_cast<float*>(smem + SM_WSQ + u * 4) = sq;
    }
    __syncthreads();

    // ---- Load this warp's B fragments ONCE (64 cols x 64 k) : 64 regs ----
    const int n_w = wid * 64;
    uint32_t Bf[4][4][4];   // [n16-group][ks][frag]
    {
        const uint32_t bb = sb + SM_WST + (uint32_t)(lane & 15) * ROW_BYTES
                          + (uint32_t)((lane >> 4) * 16);
        #pragma unroll
        for (int g = 0; g < 4; g++)
            #pragma unroll
            for (int ks = 0; ks < 4; ks++)
                ldsm_x4(Bf[g][ks][0], Bf[g][ks][1], Bf[g][ks][2], Bf[g][ks][3],
                        bb + (uint32_t)(n_w + g * 16) * ROW_BYTES + ks * 32);
    }

    const int gq = lane >> 2;           // 0..7  (C-frag row within 8-group)
    const int qq = lane & 3;            // 0..3  (C-frag col pair)

    // readback/store mapping: lane covers 4 consecutive cols of 2 rows per iter
    const int rd_row  = lane >> 4;      // 0/1
    const int rd_colg = lane & 15;      // 0..15 -> cols rd_colg*4..+3
    const float4 ws4 = *reinterpret_cast<const float4*>(
        smem + SM_WSQ + (n_w + rd_colg * 4) * 4);

    const uint32_t a_lane_off = (uint32_t)(lane & 15) * ROW_BYTES
                              + (uint32_t)((lane >> 4) * 16);
    char* const stg0 = smem + SM_STG + wid * 8192;   // two 4KB fp32 buffers

    // ---- Commit first tile (data already in registers) ----
    if (t < N_TILES) {
        #pragma unroll
        for (int it = 0; it < 8; it++) {
            const int r = it * 16 + ld_r0;
            float4 v = fv[it];
            float sq = v.x * v.x + v.y * v.y + v.z * v.z + v.w * v.w;
            sq += __shfl_xor_sync(0xffffffffu, sq, 1);
            sq += __shfl_xor_sync(0xffffffffu, sq, 2);
            sq += __shfl_xor_sync(0xffffffffu, sq, 4);
            sq += __shfl_xor_sync(0xffffffffu, sq, 8);
            uint2 pk; pk.x = pack_bf16(v.x, v.y); pk.y = pack_bf16(v.z, v.w);
            *reinterpret_cast<uint2*>(smem + SM_X0 + r * ROW_BYTES + ld_k * 2) = pk;
            if ((tid & 15) == 0)
                *reinterpret_cast<float*>(smem + SM_XSQ0 + r * 4) = sq;
        }
    }
    __syncthreads();

    int cur = 0;
    for (; t < N_TILES; t += GRID_X, cur ^= 1) {
        const int tn = t + GRID_X;
        const bool more = (tn < N_TILES);
        const uint32_t xb = cur ? SM_X1 : SM_X0;
        const uint32_t xq = cur ? SM_XSQ1 : SM_XSQ0;
        const uint32_t xbn = cur ? SM_X0 : SM_X1;
        const uint32_t xqn = cur ? SM_XSQ0 : SM_XSQ1;
        const int row0 = t * M_TILE;

        float4 pvA[4], pvB[4];
        if (more) {
            #pragma unroll
            for (int it = 0; it < 4; it++)
                pvA[it] = __ldcs(reinterpret_cast<const float4*>(
                    x + (size_t)(tn * M_TILE + it * 16 + ld_r0) * DIMK + ld_k));
        }

        #pragma unroll
        for (int rb = 0; rb < 8; rb++) {
            if (rb == 4 && more) {
                #pragma unroll
                for (int it = 0; it < 4; it++)
                    pvB[it] = __ldcs(reinterpret_cast<const float4*>(
                        x + (size_t)(tn * M_TILE + (it + 4) * 16 + ld_r0) * DIMK + ld_k));
            }
            // spread the next-tile commit: first half at rb==6 (pvA freed early)
            if (rb == 6 && more) {
                #pragma unroll
                for (int it = 0; it < 4; it++) {
                    const int r = it * 16 + ld_r0;
                    float4 v = pvA[it];
                    float sq = v.x * v.x + v.y * v.y + v.z * v.z + v.w * v.w;
                    sq += __shfl_xor_sync(0xffffffffu, sq, 1);
                    sq += __shfl_xor_sync(0xffffffffu, sq, 2);
                    sq += __shfl_xor_sync(0xffffffffu, sq, 4);
                    sq += __shfl_xor_sync(0xffffffffu, sq, 8);
                    uint2 pk; pk.x = pack_bf16(v.x, v.y); pk.y = pack_bf16(v.z, v.w);
                    *reinterpret_cast<uint2*>(smem + xbn + r * ROW_BYTES + ld_k * 2) = pk;
                    if ((tid & 15) == 0)
                        *reinterpret_cast<float*>(smem + xqn + r * 4) = sq;
                }
            }

            char* const stg = stg0 + (rb & 1) * 4096;   // double-buffered staging
            const uint32_t abase = sb + xb + (uint32_t)(rb * 16) * ROW_BYTES + a_lane_off;
            float acc[8][4];
            #pragma unroll
            for (int i = 0; i < 8; i++)
                #pragma unroll
                for (int j = 0; j < 4; j++) acc[i][j] = 0.f;

            #pragma unroll
            for (int ks = 0; ks < 4; ks++) {
                uint32_t a0, a1, a2, a3;
                ldsm_x4(a0, a1, a2, a3, abase + ks * 32);
                #pragma unroll
                for (int g = 0; g < 4; g++) {
                    mma_bf16(acc[2 * g + 0], a0, a1, a2, a3, Bf[g][ks][0], Bf[g][ks][2]);
                    mma_bf16(acc[2 * g + 1], a0, a1, a2, a3, Bf[g][ks][1], Bf[g][ks][3]);
                }
            }

            // ---- Stage raw fp32 acc (STS.64), 8B granules h ^= (gq<<2) ----
            #pragma unroll
            for (int nb = 0; nb < 8; nb++) {
                const uint32_t h  = (uint32_t)(gq * 32 + nb * 4 + qq) ^ ((uint32_t)gq << 2);
                const uint32_t hh = h + 8 * 32;   // row gq+8: same swizzle
                *reinterpret_cast<float2*>(stg + h * 8)
                    = make_float2(acc[nb][0], acc[nb][1]);
                *reinterpret_cast<float2*>(stg + hh * 8)
                    = make_float2(acc[nb][2], acc[nb][3]);
            }
            __syncwarp();
            // no trailing syncwarp: next rb uses the other staging buffer

            // ---- Read back row-major (LDS.128), epilogue, full-line STG.128 ----
            #pragma unroll
            for (int i = 0; i < 8; i++) {
                const int row = i * 2 + rd_row;
                const uint32_t g16 = (uint32_t)(row * 16 + rd_colg)
                                   ^ (((uint32_t)(row & 7)) << 1);
                const float4 v = *reinterpret_cast<const float4*>(stg + g16 * 16);
                const float xsv = *reinterpret_cast<const float*>(
                    smem + xq + (rb * 16 + row) * 4);
                float4 o;
                o.x = fmaf(-2.f, v.x, xsv + ws4.x);
                o.y = fmaf(-2.f, v.y, xsv + ws4.y);
                o.z = fmaf(-2.f, v.z, xsv + ws4.z);
                o.w = fmaf(-2.f, v.w, xsv + ws4.w);
                __stcs(reinterpret_cast<float4*>(
                    out + (size_t)(row0 + rb * 16 + row) * UNITS + n_w + rd_colg * 4), o);
            }
        }

        // ---- Commit second half of prefetched tile ----
        if (more) {
            #pragma unroll
            for (int it = 4; it < 8; it++) {
                const int r = it * 16 + ld_r0;
                float4 v = pvB[it - 4];
                float sq = v.x * v.x + v.y * v.y + v.z * v.z + v.w * v.w;
                sq += __shfl_xor_sync(0xffffffffu, sq, 1);
                sq += __shfl_xor_sync(0xffffffffu, sq, 2);
                sq += __shfl_xor_sync(0xffffffffu, sq, 4);
                sq += __shfl_xor_sync(0xffffffffu, sq, 8);
                uint2 pk; pk.x = pack_bf16(v.x, v.y); pk.y = pack_bf16(v.z, v.w);
                *reinterpret_cast<uint2*>(smem + xbn + r * ROW_BYTES + ld_k * 2) = pk;
                if ((tid & 15) == 0)
                    *reinterpret_cast<float*>(smem + xqn + r * 4) = sq;
            }
        }
        __syncthreads();
    }
}

extern "C" void kernel_launch(void* const* d_in, const int* in_sizes, int n_in,
                              void* d_out, int out_size) {
    const float* x = (const float*)d_in[0];
    const float* w = (const float*)d_in[1];
    float* out = (float*)d_out;
    cudaFuncSetAttribute(l2dist_kernel, cudaFuncAttributeMaxDynamicSharedMemorySize, SMEM_TOTAL);
    l2dist_kernel<<<GRID_X, NTHREADS, SMEM_TOTAL>>>(x, w, out);
}